// round 4
// baseline (speedup 1.0000x reference)
#include <cuda_runtime.h>

typedef unsigned long long u64;

#define Bc 256
#define Tc 1024
#define Dc 64
#define Hc 128
#define Gc 512
#define Mc (Bc*Tc)

// Scratch (device globals are the sanctioned workaround for no-alloc rule)
__device__ float g_xg[(size_t)Mc * Gc];   // [B*T, 512] gate preactivations (reused both layers)
__device__ float g_h0s[(size_t)Mc * Hc];  // [B*T, 128] layer-0 hidden outputs

// ---------- packed f32x2 helpers ----------
__device__ __forceinline__ u64 ffma2(u64 a, u64 b, u64 c) {
    u64 d; asm("fma.rn.f32x2 %0, %1, %2, %3;" : "=l"(d) : "l"(a), "l"(b), "l"(c)); return d;
}
__device__ __forceinline__ u64 pack2(float lo, float hi) {
    u64 d; asm("mov.b64 %0, {%1, %2};" : "=l"(d) : "f"(lo), "f"(hi)); return d;
}
__device__ __forceinline__ u64 dup2(float v) { return pack2(v, v); }
__device__ __forceinline__ float lo_f(u64 v) {
    unsigned a, b; asm("mov.b64 {%0, %1}, %2;" : "=r"(a), "=r"(b) : "l"(v));
    return __uint_as_float(a);
}
__device__ __forceinline__ float hi_f(u64 v) {
    unsigned a, b; asm("mov.b64 {%0, %1}, %2;" : "=r"(a), "=r"(b) : "l"(v));
    return __uint_as_float(b);
}

__device__ __forceinline__ float sigf(float x) {
    return __fdividef(1.f, 1.f + __expf(-x));
}
__device__ __forceinline__ float tanh_f(float x) {
    return 1.f - __fdividef(2.f, 1.f + __expf(2.f * x));
}

// ============================================================
// GEMM: out[m][n] = sum_k X[m][k] * W[n][k] + bias[n]
// M = 262144, N = 512, K = 64 or 128.  BM=128, BN=64, BK=64.
// 256 threads; each computes 8m x 4n via f32x2 (4 m-pairs).
// ============================================================
#define GEMM_SMEM (64*128*4 + 64*64*8)  // xs + wsd = 64KB

__global__ __launch_bounds__(256) void gemm_xw(
    const float* __restrict__ X, const float* __restrict__ W,
    const float* __restrict__ bias, float* __restrict__ out, int K)
{
    extern __shared__ float sm[];
    float* xs = sm;                        // [64][128] transposed x tile
    u64*   wsd = (u64*)(sm + 64 * 128);    // [64][64] dup'd W, permuted slots

    const int tid = threadIdx.x;
    const int tx = tid & 15;       // n dim (4 cols each)
    const int ty = tid >> 4;       // m dim (8 rows = 4 pairs each)
    const int mBase = blockIdx.x * 128;
    const int nBase = blockIdx.y * 64;

    u64 acc[4][4];
#pragma unroll
    for (int i = 0; i < 4; i++)
#pragma unroll
        for (int j = 0; j < 4; j++) acc[i][j] = 0ull;

    for (int s = 0; s < K; s += 64) {
        // load X slab [128 rows x 64 k], store transposed xs[k][m]
#pragma unroll
        for (int i = 0; i < 8; i++) {
            int L = tid + 256 * i;
            int r = L >> 4;
            int q = L & 15;
            float4 v = *(const float4*)&X[(size_t)(mBase + r) * K + s + q * 4];
            xs[(q * 4 + 0) * 128 + r] = v.x;
            xs[(q * 4 + 1) * 128 + r] = v.y;
            xs[(q * 4 + 2) * 128 + r] = v.z;
            xs[(q * 4 + 3) * 128 + r] = v.w;
        }
        // load W slab [64 n x 64 k] -> dup pairs, slot-permuted for conflict-free reads
#pragma unroll
        for (int i = 0; i < 4; i++) {
            int L = tid + 256 * i;
            int n = L >> 4;
            int q = L & 15;
            float4 v = *(const float4*)&W[(size_t)(nBase + n) * K + s + q * 4];
            int slot = ((n & 3) << 4) | (n >> 2);
            wsd[(q * 4 + 0) * 64 + slot] = dup2(v.x);
            wsd[(q * 4 + 1) * 64 + slot] = dup2(v.y);
            wsd[(q * 4 + 2) * 64 + slot] = dup2(v.z);
            wsd[(q * 4 + 3) * 64 + slot] = dup2(v.w);
        }
        __syncthreads();

#pragma unroll
        for (int k = 0; k < 64; k++) {
            u64 a0 = *(const u64*)&xs[k * 128 + ty * 8 + 0];
            u64 a1 = *(const u64*)&xs[k * 128 + ty * 8 + 2];
            u64 a2 = *(const u64*)&xs[k * 128 + ty * 8 + 4];
            u64 a3 = *(const u64*)&xs[k * 128 + ty * 8 + 6];
            u64 b0 = wsd[k * 64 + 0 * 16 + tx];
            u64 b1 = wsd[k * 64 + 1 * 16 + tx];
            u64 b2 = wsd[k * 64 + 2 * 16 + tx];
            u64 b3 = wsd[k * 64 + 3 * 16 + tx];
            acc[0][0] = ffma2(a0, b0, acc[0][0]);
            acc[0][1] = ffma2(a0, b1, acc[0][1]);
            acc[0][2] = ffma2(a0, b2, acc[0][2]);
            acc[0][3] = ffma2(a0, b3, acc[0][3]);
            acc[1][0] = ffma2(a1, b0, acc[1][0]);
            acc[1][1] = ffma2(a1, b1, acc[1][1]);
            acc[1][2] = ffma2(a1, b2, acc[1][2]);
            acc[1][3] = ffma2(a1, b3, acc[1][3]);
            acc[2][0] = ffma2(a2, b0, acc[2][0]);
            acc[2][1] = ffma2(a2, b1, acc[2][1]);
            acc[2][2] = ffma2(a2, b2, acc[2][2]);
            acc[2][3] = ffma2(a2, b3, acc[2][3]);
            acc[3][0] = ffma2(a3, b0, acc[3][0]);
            acc[3][1] = ffma2(a3, b1, acc[3][1]);
            acc[3][2] = ffma2(a3, b2, acc[3][2]);
            acc[3][3] = ffma2(a3, b3, acc[3][3]);
        }
        __syncthreads();
    }

    float4 bn = *(const float4*)&bias[nBase + tx * 4];
#pragma unroll
    for (int i = 0; i < 4; i++) {
        int m = mBase + ty * 8 + 2 * i;
        float4 lo, hi;
        lo.x = lo_f(acc[i][0]) + bn.x;
        lo.y = lo_f(acc[i][1]) + bn.y;
        lo.z = lo_f(acc[i][2]) + bn.z;
        lo.w = lo_f(acc[i][3]) + bn.w;
        hi.x = hi_f(acc[i][0]) + bn.x;
        hi.y = hi_f(acc[i][1]) + bn.y;
        hi.z = hi_f(acc[i][2]) + bn.z;
        hi.w = hi_f(acc[i][3]) + bn.w;
        *(float4*)&out[(size_t)m * Gc + nBase + tx * 4] = lo;
        *(float4*)&out[(size_t)(m + 1) * Gc + nBase + tx * 4] = hi;
    }
}

// ============================================================
// LSTM recurrence: persistent, 1 CTA per 2 batch elements.
// 256 threads; thread j owns gate rows (2j, 2j+1) packed f32x2.
// w_hh split: k=0..63 in smem (transposed pairs), k=64..127 in regs.
// ============================================================
#define REC_SMEM (64*256*8 + 2*128*8 + 2*512*4)  // wt + hdup + gbuf = 137216

__global__ __launch_bounds__(256, 1) void lstm_rec(
    const float* __restrict__ xg, const float* __restrict__ whh,
    const float* __restrict__ h0, float* __restrict__ hout,
    const float* __restrict__ fcw, const float* __restrict__ fcb,
    float* __restrict__ outp, int is_l0)
{
    extern __shared__ char smraw[];
    u64*   wt = (u64*)smraw;                           // [64][256] (k, row-pair)
    u64*   hd = (u64*)(smraw + 64 * 256 * 8);          // [2][128] (h,h) dup
    float* gb = (float*)(smraw + 64 * 256 * 8 + 2 * 128 * 8);  // [2][512]

    const int tid = threadIdx.x;
    const int b0 = blockIdx.x * 2;
    const int pb = tid >> 7;        // pointwise batch
    const int pidx = tid & 127;     // pointwise h index

    // --- init smem weights (k = 0..63), transposed pairs ---
#pragma unroll
    for (int kq = 0; kq < 16; kq++) {
        float4 r0 = *(const float4*)&whh[(size_t)(2 * tid) * Hc + kq * 4];
        float4 r1 = *(const float4*)&whh[(size_t)(2 * tid + 1) * Hc + kq * 4];
        wt[(kq * 4 + 0) * 256 + tid] = pack2(r0.x, r1.x);
        wt[(kq * 4 + 1) * 256 + tid] = pack2(r0.y, r1.y);
        wt[(kq * 4 + 2) * 256 + tid] = pack2(r0.z, r1.z);
        wt[(kq * 4 + 3) * 256 + tid] = pack2(r0.w, r1.w);
    }
    // --- register weights (k = 64..127) ---
    u64 wreg[64];
#pragma unroll
    for (int kq = 0; kq < 16; kq++) {
        float4 r0 = *(const float4*)&whh[(size_t)(2 * tid) * Hc + 64 + kq * 4];
        float4 r1 = *(const float4*)&whh[(size_t)(2 * tid + 1) * Hc + 64 + kq * 4];
        wreg[kq * 4 + 0] = pack2(r0.x, r1.x);
        wreg[kq * 4 + 1] = pack2(r0.y, r1.y);
        wreg[kq * 4 + 2] = pack2(r0.z, r1.z);
        wreg[kq * 4 + 3] = pack2(r0.w, r1.w);
    }
    // --- init h ---
    {
        float h = h0[(size_t)(b0 + pb) * Hc + pidx];
        hd[pb * 128 + pidx] = dup2(h);
    }
    float c = 0.f;
    __syncthreads();

    const float* xg0p = xg + (size_t)b0 * Tc * Gc + 2 * tid;
    const float* xg1p = xg + (size_t)(b0 + 1) * Tc * Gc + 2 * tid;
    u64 xc0 = *(const u64*)xg0p;
    u64 xc1 = *(const u64*)xg1p;

#pragma unroll 1
    for (int t = 0; t < Tc; t++) {
        int tn = (t + 1 < Tc) ? (t + 1) : t;
        u64 xn0 = *(const u64*)(xg0p + (size_t)tn * Gc);   // prefetch next step
        u64 xn1 = *(const u64*)(xg1p + (size_t)tn * Gc);

        u64 acc0 = xc0, acc1 = xc1;
#pragma unroll
        for (int k = 0; k < 64; k++) {
            u64 w = wt[k * 256 + tid];
            acc0 = ffma2(w, hd[k], acc0);
            acc1 = ffma2(w, hd[128 + k], acc1);
        }
#pragma unroll
        for (int k = 0; k < 64; k++) {
            acc0 = ffma2(wreg[k], hd[64 + k], acc0);
            acc1 = ffma2(wreg[k], hd[192 + k], acc1);
        }
        *(u64*)&gb[0 * 512 + 2 * tid] = acc0;
        *(u64*)&gb[1 * 512 + 2 * tid] = acc1;
        __syncthreads();

        // pointwise: all 256 threads, (pb, pidx)
        {
            float gi = gb[pb * 512 + pidx];
            float gf = gb[pb * 512 + 128 + pidx];
            float gg = gb[pb * 512 + 256 + pidx];
            float go = gb[pb * 512 + 384 + pidx];
            float ig = sigf(gi), fg = sigf(gf), cg = tanh_f(gg), og = sigf(go);
            c = fg * c + ig * cg;
            float h = og * tanh_f(c);
            hd[pb * 128 + pidx] = dup2(h);
            if (is_l0)
                hout[((size_t)(b0 + pb) * Tc + t) * Hc + pidx] = h;
        }
        __syncthreads();
        xc0 = xn0;
        xc1 = xn1;
    }

    if (!is_l0) {
        float h = lo_f(hd[pb * 128 + pidx]);
        gb[tid] = h * fcw[pidx];
        __syncthreads();
        if (tid < 2) {
            float s = fcb[0];
            for (int i = 0; i < 128; i++) s += gb[tid * 128 + i];
            outp[b0 + tid] = s;
        }
    }
}

extern "C" void kernel_launch(void* const* d_in, const int* in_sizes, int n_in,
                              void* d_out, int out_size) {
    const float* x    = (const float*)d_in[0];
    const float* h0   = (const float*)d_in[1];
    const float* wih0 = (const float*)d_in[2];
    const float* whh0 = (const float*)d_in[3];
    const float* b0_  = (const float*)d_in[4];
    const float* wih1 = (const float*)d_in[5];
    const float* whh1 = (const float*)d_in[6];
    const float* b1_  = (const float*)d_in[7];
    const float* fcw  = (const float*)d_in[8];
    const float* fcb  = (const float*)d_in[9];
    float* out = (float*)d_out;

    cudaFuncSetAttribute(gemm_xw, cudaFuncAttributeMaxDynamicSharedMemorySize, GEMM_SMEM);
    cudaFuncSetAttribute(lstm_rec, cudaFuncAttributeMaxDynamicSharedMemorySize, REC_SMEM);

    float *xgp, *h0sp;
    cudaGetSymbolAddress((void**)&xgp, g_xg);
    cudaGetSymbolAddress((void**)&h0sp, g_h0s);

    // layer 0: input GEMM (K=64) then recurrence
    gemm_xw<<<dim3(Mc / 128, Gc / 64), 256, GEMM_SMEM>>>(x, wih0, b0_, xgp, 64);
    lstm_rec<<<Bc / 2, 256, REC_SMEM>>>(xgp, whh0, h0, h0sp,
                                        nullptr, nullptr, nullptr, 1);
    // layer 1: input GEMM (K=128) then recurrence + fc head
    gemm_xw<<<dim3(Mc / 128, Gc / 64), 256, GEMM_SMEM>>>(h0sp, wih1, b1_, xgp, 128);
    lstm_rec<<<Bc / 2, 256, REC_SMEM>>>(xgp, whh1, h0 + (size_t)Bc * Hc, nullptr,
                                        fcw, fcb, out, 0);
}